// round 2
// baseline (speedup 1.0000x reference)
#include <cuda_runtime.h>
#include <cuda_bf16.h>
#include <cstdint>

// ============================================================================
// out[b,c] = xs[b] + ps[c] - 2 * dot(x_b, p_c)
//   x = 3*l2norm(inputs) [4096,128], p = 3*l2norm(kernel) [16384,128]
// tcgen05 is NOT available (harness targets plain sm_103 PTX) -> legacy
// mma.sync.m16n8k16 bf16 path with ldmatrix + XOR-swizzled SMEM.
// ============================================================================

static constexpr int B_ROWS = 4096;
static constexpr int C_ROWS = 16384;
static constexpr int D_DIM  = 128;

static constexpr int MT = 128;    // CTA M tile
static constexpr int NT = 256;    // CTA N tile
// warp grid 4(M) x 4(N); warp tile 32 x 64

static constexpr int SMEM_A_OFF = 0;
static constexpr int SMEM_A_BYTES = MT * D_DIM * 2;          // 32768
static constexpr int SMEM_B_OFF = SMEM_A_BYTES;              // 32768
static constexpr int SMEM_B_BYTES = NT * D_DIM * 2;          // 65536
static constexpr int SMEM_TOTAL = SMEM_A_BYTES + SMEM_B_BYTES; // 98304

// ---------------- scratch (no allocation allowed) ----------------
__device__ __nv_bfloat16 g_x[B_ROWS * D_DIM];
__device__ __nv_bfloat16 g_p[C_ROWS * D_DIM];
__device__ float g_xs[B_ROWS];
__device__ float g_ps[C_ROWS];

__device__ __forceinline__ uint32_t smem_u32(const void* p) {
    uint32_t a;
    asm("{ .reg .u64 t; cvta.to.shared.u64 t, %1; cvt.u32.u64 %0, t; }" : "=r"(a) : "l"(p));
    return a;
}

__device__ __forceinline__ void ldmatrix_x4(uint32_t& r0, uint32_t& r1,
                                            uint32_t& r2, uint32_t& r3, uint32_t addr) {
    asm volatile("ldmatrix.sync.aligned.m8n8.x4.shared.b16 {%0,%1,%2,%3}, [%4];"
                 : "=r"(r0), "=r"(r1), "=r"(r2), "=r"(r3) : "r"(addr));
}

__device__ __forceinline__ void mma_bf16(float& c0, float& c1, float& c2, float& c3,
                                         uint32_t a0, uint32_t a1, uint32_t a2, uint32_t a3,
                                         uint32_t b0, uint32_t b1) {
    asm volatile(
        "mma.sync.aligned.m16n8k16.row.col.f32.bf16.bf16.f32 "
        "{%0,%1,%2,%3}, {%4,%5,%6,%7}, {%8,%9}, {%0,%1,%2,%3};"
        : "+f"(c0), "+f"(c1), "+f"(c2), "+f"(c3)
        : "r"(a0), "r"(a1), "r"(a2), "r"(a3), "r"(b0), "r"(b1));
}

// ============================================================================
// Kernel 1: normalize rows -> bf16 + per-row sum-of-squares (fp32)
// ============================================================================
__global__ __launch_bounds__(256)
void normalize_kernel(const float* __restrict__ in, int rows, int which) {
    __nv_bfloat16* outv = which ? g_p : g_x;
    float* outs = which ? g_ps : g_xs;

    int warp = (blockIdx.x * blockDim.x + threadIdx.x) >> 5;
    int lane = threadIdx.x & 31;
    if (warp >= rows) return;

    float4 v = reinterpret_cast<const float4*>(in + (size_t)warp * D_DIM)[lane];
    float ss = v.x * v.x + v.y * v.y + v.z * v.z + v.w * v.w;
    #pragma unroll
    for (int o = 16; o; o >>= 1) ss += __shfl_xor_sync(0xffffffffu, ss, o);

    float r = rsqrtf(fmaxf(ss, 1e-12f));
    float s = 3.0f * r;
    __nv_bfloat162 h0 = __floats2bfloat162_rn(v.x * s, v.y * s);
    __nv_bfloat162 h1 = __floats2bfloat162_rn(v.z * s, v.w * s);
    uint2 pk;
    pk.x = *reinterpret_cast<uint32_t*>(&h0);
    pk.y = *reinterpret_cast<uint32_t*>(&h1);
    reinterpret_cast<uint2*>(outv + (size_t)warp * D_DIM)[lane] = pk;

    if (lane == 0) outs[warp] = 9.0f * ss * r * r;  // == sum(x*x), ~9.0
}

// ============================================================================
// Kernel 2: bf16 mma.sync GEMM, CTA tile 128x256, K=128 resident in SMEM,
//           fused distance epilogue.
// SMEM layout: row-major, 256B (=16 chunks of 16B) per row,
//   chunk c of row r stored at phys chunk (c ^ (r & 7))  -> ldmatrix conflict-free.
// ============================================================================
__global__ __launch_bounds__(512, 1)
void gemm_kernel(float* __restrict__ out) {
    extern __shared__ char smem[];
    const uint32_t sb = smem_u32(smem);

    const int tid  = threadIdx.x;
    const int lane = tid & 31;
    const int wid  = tid >> 5;
    const int warp_m = wid & 3;   // 0..3 -> M offset 32*warp_m
    const int warp_n = wid >> 2;  // 0..3 -> N offset 64*warp_n

    const int m0 = blockIdx.y * MT;
    const int n0 = blockIdx.x * NT;

    // ---- load A tile: 128 rows x 16 chunks (16B) ----
    {
        const uint4* src = reinterpret_cast<const uint4*>(g_x + (size_t)m0 * D_DIM);
        #pragma unroll
        for (int it = 0; it < 4; it++) {
            int i = it * 512 + tid;          // 2048 chunks
            int row = i >> 4, c = i & 15;
            uint4 val = src[i];
            *reinterpret_cast<uint4*>(smem + SMEM_A_OFF + row * 256 + ((c ^ (row & 7)) << 4)) = val;
        }
    }
    // ---- load B tile: 256 rows x 16 chunks ----
    {
        const uint4* src = reinterpret_cast<const uint4*>(g_p + (size_t)n0 * D_DIM);
        #pragma unroll
        for (int it = 0; it < 8; it++) {
            int i = it * 512 + tid;          // 4096 chunks
            int row = i >> 4, c = i & 15;
            uint4 val = src[i];
            *reinterpret_cast<uint4*>(smem + SMEM_B_OFF + row * 256 + ((c ^ (row & 7)) << 4)) = val;
        }
    }
    __syncthreads();

    float acc[2][8][4];
    #pragma unroll
    for (int mi = 0; mi < 2; mi++)
        #pragma unroll
        for (int ni = 0; ni < 8; ni++)
            #pragma unroll
            for (int k = 0; k < 4; k++) acc[mi][ni][k] = 0.0f;

    // precompute ldmatrix lane address components
    // A: row = warp_m*32 + mi*16 + (lane&7) + ((lane>>3)&1)*8 ; kchunk = ks*2 + (lane>>4)
    const int a_row_base = warp_m * 32 + (lane & 7) + ((lane >> 3) & 1) * 8;
    const int a_kc_lane  = (lane >> 4);
    // B: row = warp_n*64 + g*16 + (lane&7) + (lane>>4)*8 ; kchunk = ks*2 + ((lane>>3)&1)
    const int b_row_base = warp_n * 64 + (lane & 7) + (lane >> 4) * 8;
    const int b_kc_lane  = ((lane >> 3) & 1);

    #pragma unroll
    for (int ks = 0; ks < 8; ks++) {
        uint32_t a[2][4];
        #pragma unroll
        for (int mi = 0; mi < 2; mi++) {
            int row = a_row_base + mi * 16;
            int kc  = ks * 2 + a_kc_lane;
            uint32_t addr = sb + SMEM_A_OFF + row * 256 + ((kc ^ (row & 7)) << 4);
            ldmatrix_x4(a[mi][0], a[mi][1], a[mi][2], a[mi][3], addr);
        }
        uint32_t b[8][2];
        #pragma unroll
        for (int g = 0; g < 4; g++) {
            int row = b_row_base + g * 16;
            int kc  = ks * 2 + b_kc_lane;
            uint32_t addr = sb + SMEM_B_OFF + row * 256 + ((kc ^ (row & 7)) << 4);
            ldmatrix_x4(b[2 * g][0], b[2 * g][1], b[2 * g + 1][0], b[2 * g + 1][1], addr);
        }
        #pragma unroll
        for (int mi = 0; mi < 2; mi++)
            #pragma unroll
            for (int ni = 0; ni < 8; ni++)
                mma_bf16(acc[mi][ni][0], acc[mi][ni][1], acc[mi][ni][2], acc[mi][ni][3],
                         a[mi][0], a[mi][1], a[mi][2], a[mi][3],
                         b[ni][0], b[ni][1]);
    }

    // ---- epilogue: out = xs[m] + ps[n] - 2*acc ----
    const int c_base = n0 + warp_n * 64 + (lane & 3) * 2;
    float2 ps[8];
    #pragma unroll
    for (int ni = 0; ni < 8; ni++)
        ps[ni] = *reinterpret_cast<const float2*>(g_ps + c_base + ni * 8);

    #pragma unroll
    for (int mi = 0; mi < 2; mi++) {
        int r0 = m0 + warp_m * 32 + mi * 16 + (lane >> 2);
        float xs0 = g_xs[r0];
        float xs1 = g_xs[r0 + 8];
        float* o0 = out + (size_t)r0 * C_ROWS + c_base;
        float* o1 = out + (size_t)(r0 + 8) * C_ROWS + c_base;
        #pragma unroll
        for (int ni = 0; ni < 8; ni++) {
            float2 v0, v1;
            v0.x = xs0 + ps[ni].x - 2.0f * acc[mi][ni][0];
            v0.y = xs0 + ps[ni].y - 2.0f * acc[mi][ni][1];
            v1.x = xs1 + ps[ni].x - 2.0f * acc[mi][ni][2];
            v1.y = xs1 + ps[ni].y - 2.0f * acc[mi][ni][3];
            *reinterpret_cast<float2*>(o0 + ni * 8) = v0;
            *reinterpret_cast<float2*>(o1 + ni * 8) = v1;
        }
    }
}

// ============================================================================
extern "C" void kernel_launch(void* const* d_in, const int* in_sizes, int n_in,
                              void* d_out, int out_size) {
    (void)in_sizes; (void)n_in; (void)out_size;
    const float* inp = (const float*)d_in[0];   // inputs [4096,128] fp32
    const float* ker = (const float*)d_in[1];   // kernel [16384,128] fp32
    float* out = (float*)d_out;                 // [4096,16384] fp32

    cudaFuncSetAttribute(gemm_kernel, cudaFuncAttributeMaxDynamicSharedMemorySize, SMEM_TOTAL);

    normalize_kernel<<<(B_ROWS * 32 + 255) / 256, 256>>>(inp, B_ROWS, 0);
    normalize_kernel<<<(C_ROWS * 32 + 255) / 256, 256>>>(ker, C_ROWS, 1);

    dim3 grid(C_ROWS / NT, B_ROWS / MT);   // 64 x 32
    gemm_kernel<<<grid, 512, SMEM_TOTAL>>>(out);
}

// round 3
// speedup vs baseline: 1.2561x; 1.2561x over previous
#include <cuda_runtime.h>
#include <cuda_bf16.h>
#include <cstdint>

// ============================================================================
// out[b,c] = xs[b] + ps[c] - 2 * dot(x_b, p_c)
//   x = 3*l2norm(inputs) [4096,128], p = 3*l2norm(kernel) [16384,128]
// Legacy mma.sync.m16n8k16 bf16 (tcgen05 unavailable on plain sm_103 target).
// R3: 128x128 tiles / 256 thr -> 2 CTAs/SM for phase overlap; cp.async loads;
//     fused normalize.
// ============================================================================

static constexpr int B_ROWS = 4096;
static constexpr int C_ROWS = 16384;
static constexpr int D_DIM  = 128;

static constexpr int MT = 128;    // CTA M tile
static constexpr int NT = 128;    // CTA N tile
// warp grid 4(M) x 2(N); warp tile 32 x 64

static constexpr int SMEM_A_OFF = 0;
static constexpr int SMEM_A_BYTES = MT * D_DIM * 2;            // 32768
static constexpr int SMEM_B_OFF = SMEM_A_BYTES;                // 32768
static constexpr int SMEM_B_BYTES = NT * D_DIM * 2;            // 32768
static constexpr int SMEM_TOTAL = SMEM_A_BYTES + SMEM_B_BYTES; // 65536

// ---------------- scratch (no allocation allowed) ----------------
__device__ __nv_bfloat16 g_x[B_ROWS * D_DIM];
__device__ __nv_bfloat16 g_p[C_ROWS * D_DIM];
__device__ float g_xs[B_ROWS];
__device__ float g_ps[C_ROWS];

__device__ __forceinline__ uint32_t smem_u32(const void* p) {
    uint32_t a;
    asm("{ .reg .u64 t; cvta.to.shared.u64 t, %1; cvt.u32.u64 %0, t; }" : "=r"(a) : "l"(p));
    return a;
}

__device__ __forceinline__ void cp_async16(uint32_t dst, const void* src) {
    asm volatile("cp.async.cg.shared.global [%0], [%1], 16;" :: "r"(dst), "l"(src));
}

__device__ __forceinline__ void ldmatrix_x4(uint32_t& r0, uint32_t& r1,
                                            uint32_t& r2, uint32_t& r3, uint32_t addr) {
    asm volatile("ldmatrix.sync.aligned.m8n8.x4.shared.b16 {%0,%1,%2,%3}, [%4];"
                 : "=r"(r0), "=r"(r1), "=r"(r2), "=r"(r3) : "r"(addr));
}

__device__ __forceinline__ void mma_bf16(float& c0, float& c1, float& c2, float& c3,
                                         uint32_t a0, uint32_t a1, uint32_t a2, uint32_t a3,
                                         uint32_t b0, uint32_t b1) {
    asm volatile(
        "mma.sync.aligned.m16n8k16.row.col.f32.bf16.bf16.f32 "
        "{%0,%1,%2,%3}, {%4,%5,%6,%7}, {%8,%9}, {%0,%1,%2,%3};"
        : "+f"(c0), "+f"(c1), "+f"(c2), "+f"(c3)
        : "r"(a0), "r"(a1), "r"(a2), "r"(a3), "r"(b0), "r"(b1));
}

// ============================================================================
// Kernel 1: normalize ALL rows (inputs then kernel) -> bf16 + row sum-of-squares
// ============================================================================
__global__ __launch_bounds__(256)
void normalize_kernel(const float* __restrict__ inp, const float* __restrict__ ker) {
    int warp = (blockIdx.x * blockDim.x + threadIdx.x) >> 5;
    int lane = threadIdx.x & 31;
    if (warp >= B_ROWS + C_ROWS) return;

    const float* src;
    __nv_bfloat16* outv;
    float* outs;
    int row;
    if (warp < B_ROWS) { src = inp; outv = g_x; outs = g_xs; row = warp; }
    else { src = ker; outv = g_p; outs = g_ps; row = warp - B_ROWS; }

    float4 v = reinterpret_cast<const float4*>(src + (size_t)row * D_DIM)[lane];
    float ss = v.x * v.x + v.y * v.y + v.z * v.z + v.w * v.w;
    #pragma unroll
    for (int o = 16; o; o >>= 1) ss += __shfl_xor_sync(0xffffffffu, ss, o);

    float r = rsqrtf(fmaxf(ss, 1e-12f));
    float s = 3.0f * r;
    __nv_bfloat162 h0 = __floats2bfloat162_rn(v.x * s, v.y * s);
    __nv_bfloat162 h1 = __floats2bfloat162_rn(v.z * s, v.w * s);
    uint2 pk;
    pk.x = *reinterpret_cast<uint32_t*>(&h0);
    pk.y = *reinterpret_cast<uint32_t*>(&h1);
    reinterpret_cast<uint2*>(outv + (size_t)row * D_DIM)[lane] = pk;

    if (lane == 0) outs[row] = 9.0f * ss * r * r;   // == sum(x*x)
}

// ============================================================================
// Kernel 2: bf16 mma.sync GEMM, CTA tile 128x128, K=128 resident in SMEM,
//           fused distance epilogue. 2 CTAs/SM for load/compute/store overlap.
// SMEM: 256B/row = 16 chunks of 16B; chunk c of row r at phys (c ^ (r & 7)).
// ============================================================================
__global__ __launch_bounds__(256, 2)
void gemm_kernel(float* __restrict__ out) {
    extern __shared__ char smem[];
    const uint32_t sb = smem_u32(smem);

    const int tid  = threadIdx.x;
    const int lane = tid & 31;
    const int wid  = tid >> 5;
    const int warp_m = wid & 3;   // 0..3 -> M offset 32*warp_m
    const int warp_n = wid >> 2;  // 0..1 -> N offset 64*warp_n

    const int m0 = blockIdx.y * MT;
    const int n0 = blockIdx.x * NT;

    // ---- async load A + B tiles (each 128 rows x 16 chunks of 16B) ----
    {
        const char* srcA = reinterpret_cast<const char*>(g_x) + (size_t)m0 * 256;
        const char* srcB = reinterpret_cast<const char*>(g_p) + (size_t)n0 * 256;
        #pragma unroll
        for (int it = 0; it < 8; it++) {
            int i = it * 256 + tid;            // 2048 chunks each
            int row = i >> 4, c = i & 15;
            uint32_t doff = row * 256 + ((c ^ (row & 7)) << 4);
            cp_async16(sb + SMEM_A_OFF + doff, srcA + (size_t)row * 256 + c * 16);
            cp_async16(sb + SMEM_B_OFF + doff, srcB + (size_t)row * 256 + c * 16);
        }
    }
    asm volatile("cp.async.commit_group;");
    asm volatile("cp.async.wait_group 0;" ::: "memory");
    __syncthreads();

    float acc[2][8][4];
    #pragma unroll
    for (int mi = 0; mi < 2; mi++)
        #pragma unroll
        for (int ni = 0; ni < 8; ni++)
            #pragma unroll
            for (int k = 0; k < 4; k++) acc[mi][ni][k] = 0.0f;

    const int a_row_base = warp_m * 32 + (lane & 7) + ((lane >> 3) & 1) * 8;
    const int a_kc_lane  = (lane >> 4);
    const int b_row_base = warp_n * 64 + (lane & 7) + (lane >> 4) * 8;
    const int b_kc_lane  = ((lane >> 3) & 1);

    #pragma unroll
    for (int ks = 0; ks < 8; ks++) {
        uint32_t a[2][4];
        #pragma unroll
        for (int mi = 0; mi < 2; mi++) {
            int row = a_row_base + mi * 16;
            int kc  = ks * 2 + a_kc_lane;
            uint32_t addr = sb + SMEM_A_OFF + row * 256 + ((kc ^ (row & 7)) << 4);
            ldmatrix_x4(a[mi][0], a[mi][1], a[mi][2], a[mi][3], addr);
        }
        uint32_t b[8][2];
        #pragma unroll
        for (int g = 0; g < 4; g++) {
            int row = b_row_base + g * 16;
            int kc  = ks * 2 + b_kc_lane;
            uint32_t addr = sb + SMEM_B_OFF + row * 256 + ((kc ^ (row & 7)) << 4);
            ldmatrix_x4(b[2 * g][0], b[2 * g][1], b[2 * g + 1][0], b[2 * g + 1][1], addr);
        }
        #pragma unroll
        for (int mi = 0; mi < 2; mi++)
            #pragma unroll
            for (int ni = 0; ni < 8; ni++)
                mma_bf16(acc[mi][ni][0], acc[mi][ni][1], acc[mi][ni][2], acc[mi][ni][3],
                         a[mi][0], a[mi][1], a[mi][2], a[mi][3],
                         b[ni][0], b[ni][1]);
    }

    // ---- epilogue: out = xs[m] + ps[n] - 2*acc ----
    const int c_base = n0 + warp_n * 64 + (lane & 3) * 2;
    float2 ps[8];
    #pragma unroll
    for (int ni = 0; ni < 8; ni++)
        ps[ni] = *reinterpret_cast<const float2*>(g_ps + c_base + ni * 8);

    #pragma unroll
    for (int mi = 0; mi < 2; mi++) {
        int r0 = m0 + warp_m * 32 + mi * 16 + (lane >> 2);
        float xs0 = g_xs[r0];
        float xs1 = g_xs[r0 + 8];
        float* o0 = out + (size_t)r0 * C_ROWS + c_base;
        float* o1 = out + (size_t)(r0 + 8) * C_ROWS + c_base;
        #pragma unroll
        for (int ni = 0; ni < 8; ni++) {
            float2 v0, v1;
            v0.x = xs0 + ps[ni].x - 2.0f * acc[mi][ni][0];
            v0.y = xs0 + ps[ni].y - 2.0f * acc[mi][ni][1];
            v1.x = xs1 + ps[ni].x - 2.0f * acc[mi][ni][2];
            v1.y = xs1 + ps[ni].y - 2.0f * acc[mi][ni][3];
            *reinterpret_cast<float2*>(o0 + ni * 8) = v0;
            *reinterpret_cast<float2*>(o1 + ni * 8) = v1;
        }
    }
}

// ============================================================================
extern "C" void kernel_launch(void* const* d_in, const int* in_sizes, int n_in,
                              void* d_out, int out_size) {
    (void)in_sizes; (void)n_in; (void)out_size;
    const float* inp = (const float*)d_in[0];   // inputs [4096,128] fp32
    const float* ker = (const float*)d_in[1];   // kernel [16384,128] fp32
    float* out = (float*)d_out;                 // [4096,16384] fp32

    cudaFuncSetAttribute(gemm_kernel, cudaFuncAttributeMaxDynamicSharedMemorySize, SMEM_TOTAL);

    int total_warps = B_ROWS + C_ROWS;
    normalize_kernel<<<(total_warps * 32 + 255) / 256, 256>>>(inp, ker);

    dim3 grid(C_ROWS / NT, B_ROWS / MT);   // 128 x 32
    gemm_kernel<<<grid, 256, SMEM_TOTAL>>>(out);
}

// round 4
// speedup vs baseline: 1.3055x; 1.0394x over previous
#include <cuda_runtime.h>
#include <cuda_bf16.h>
#include <cstdint>

// ============================================================================
// out[b,c] = xs[b] + ps[c] - 2 * dot(x_b, p_c)
//   x = 3*l2norm(inputs) [4096,128], p = 3*l2norm(kernel) [16384,128]
// Legacy mma.sync.m16n8k16 bf16 (tcgen05 unavailable on plain sm_103 target).
// R4: square 64x64 warp tiles (4 warps/CTA, 128 thr) to cut cross-warp
//     ldmatrix re-read redundancy 192KB->128KB per tile; 2 CTAs/SM overlap.
// ============================================================================

static constexpr int B_ROWS = 4096;
static constexpr int C_ROWS = 16384;
static constexpr int D_DIM  = 128;

static constexpr int MT = 128;    // CTA M tile
static constexpr int NT = 128;    // CTA N tile
// warp grid 2(M) x 2(N); warp tile 64 x 64

static constexpr int SMEM_A_OFF = 0;
static constexpr int SMEM_A_BYTES = MT * D_DIM * 2;            // 32768
static constexpr int SMEM_B_OFF = SMEM_A_BYTES;                // 32768
static constexpr int SMEM_B_BYTES = NT * D_DIM * 2;            // 32768
static constexpr int SMEM_TOTAL = SMEM_A_BYTES + SMEM_B_BYTES; // 65536

// ---------------- scratch (no allocation allowed) ----------------
__device__ __nv_bfloat16 g_x[B_ROWS * D_DIM];
__device__ __nv_bfloat16 g_p[C_ROWS * D_DIM];
__device__ float g_xs[B_ROWS];
__device__ float g_ps[C_ROWS];

__device__ __forceinline__ uint32_t smem_u32(const void* p) {
    uint32_t a;
    asm("{ .reg .u64 t; cvta.to.shared.u64 t, %1; cvt.u32.u64 %0, t; }" : "=r"(a) : "l"(p));
    return a;
}

__device__ __forceinline__ void cp_async16(uint32_t dst, const void* src) {
    asm volatile("cp.async.cg.shared.global [%0], [%1], 16;" :: "r"(dst), "l"(src));
}

__device__ __forceinline__ void ldmatrix_x4(uint32_t& r0, uint32_t& r1,
                                            uint32_t& r2, uint32_t& r3, uint32_t addr) {
    asm volatile("ldmatrix.sync.aligned.m8n8.x4.shared.b16 {%0,%1,%2,%3}, [%4];"
                 : "=r"(r0), "=r"(r1), "=r"(r2), "=r"(r3) : "r"(addr));
}

__device__ __forceinline__ void mma_bf16(float& c0, float& c1, float& c2, float& c3,
                                         uint32_t a0, uint32_t a1, uint32_t a2, uint32_t a3,
                                         uint32_t b0, uint32_t b1) {
    asm volatile(
        "mma.sync.aligned.m16n8k16.row.col.f32.bf16.bf16.f32 "
        "{%0,%1,%2,%3}, {%4,%5,%6,%7}, {%8,%9}, {%0,%1,%2,%3};"
        : "+f"(c0), "+f"(c1), "+f"(c2), "+f"(c3)
        : "r"(a0), "r"(a1), "r"(a2), "r"(a3), "r"(b0), "r"(b1));
}

// ============================================================================
// Kernel 1: normalize ALL rows -> bf16 + per-row sum-of-squares
// ============================================================================
__global__ __launch_bounds__(256)
void normalize_kernel(const float* __restrict__ inp, const float* __restrict__ ker) {
    int warp = (blockIdx.x * blockDim.x + threadIdx.x) >> 5;
    int lane = threadIdx.x & 31;
    if (warp >= B_ROWS + C_ROWS) return;

    const float* src;
    __nv_bfloat16* outv;
    float* outs;
    int row;
    if (warp < B_ROWS) { src = inp; outv = g_x; outs = g_xs; row = warp; }
    else { src = ker; outv = g_p; outs = g_ps; row = warp - B_ROWS; }

    float4 v = reinterpret_cast<const float4*>(src + (size_t)row * D_DIM)[lane];
    float ss = v.x * v.x + v.y * v.y + v.z * v.z + v.w * v.w;
    #pragma unroll
    for (int o = 16; o; o >>= 1) ss += __shfl_xor_sync(0xffffffffu, ss, o);

    float r = rsqrtf(fmaxf(ss, 1e-12f));
    float s = 3.0f * r;
    __nv_bfloat162 h0 = __floats2bfloat162_rn(v.x * s, v.y * s);
    __nv_bfloat162 h1 = __floats2bfloat162_rn(v.z * s, v.w * s);
    uint2 pk;
    pk.x = *reinterpret_cast<uint32_t*>(&h0);
    pk.y = *reinterpret_cast<uint32_t*>(&h1);
    reinterpret_cast<uint2*>(outv + (size_t)row * D_DIM)[lane] = pk;

    if (lane == 0) outs[row] = 9.0f * ss * r * r;   // == sum(x*x)
}

// ============================================================================
// Kernel 2: bf16 mma.sync GEMM, CTA 128x128, 4 warps @ 64x64, K=128 in SMEM,
//           fused distance epilogue. 2 CTAs/SM.
// SMEM: 256B/row = 16 chunks of 16B; chunk c of row r at phys (c ^ (r & 7)).
// ============================================================================
__global__ __launch_bounds__(128, 2)
void gemm_kernel(float* __restrict__ out) {
    extern __shared__ char smem[];
    const uint32_t sb = smem_u32(smem);

    const int tid  = threadIdx.x;
    const int lane = tid & 31;
    const int wid  = tid >> 5;
    const int warp_m = wid & 1;   // 0..1 -> M offset 64*warp_m
    const int warp_n = wid >> 1;  // 0..1 -> N offset 64*warp_n

    const int m0 = blockIdx.y * MT;
    const int n0 = blockIdx.x * NT;

    // ---- async load A + B tiles (each 128 rows x 16 chunks of 16B) ----
    {
        const char* srcA = reinterpret_cast<const char*>(g_x) + (size_t)m0 * 256;
        const char* srcB = reinterpret_cast<const char*>(g_p) + (size_t)n0 * 256;
        #pragma unroll
        for (int it = 0; it < 16; it++) {
            int i = it * 128 + tid;            // 2048 chunks each
            int row = i >> 4, c = i & 15;
            uint32_t doff = row * 256 + ((c ^ (row & 7)) << 4);
            cp_async16(sb + SMEM_A_OFF + doff, srcA + (size_t)row * 256 + c * 16);
            cp_async16(sb + SMEM_B_OFF + doff, srcB + (size_t)row * 256 + c * 16);
        }
    }
    asm volatile("cp.async.commit_group;");
    asm volatile("cp.async.wait_group 0;" ::: "memory");
    __syncthreads();

    float acc[4][8][4];
    #pragma unroll
    for (int mi = 0; mi < 4; mi++)
        #pragma unroll
        for (int ni = 0; ni < 8; ni++)
            #pragma unroll
            for (int k = 0; k < 4; k++) acc[mi][ni][k] = 0.0f;

    const int a_row_base = warp_m * 64 + (lane & 7) + ((lane >> 3) & 1) * 8;
    const int a_kc_lane  = (lane >> 4);
    const int b_row_base = warp_n * 64 + (lane & 7) + (lane >> 4) * 8;
    const int b_kc_lane  = ((lane >> 3) & 1);

    #pragma unroll
    for (int ks = 0; ks < 8; ks++) {
        uint32_t a[4][4];
        #pragma unroll
        for (int mi = 0; mi < 4; mi++) {
            int row = a_row_base + mi * 16;
            int kc  = ks * 2 + a_kc_lane;
            uint32_t addr = sb + SMEM_A_OFF + row * 256 + ((kc ^ (row & 7)) << 4);
            ldmatrix_x4(a[mi][0], a[mi][1], a[mi][2], a[mi][3], addr);
        }
        uint32_t b[8][2];
        #pragma unroll
        for (int g = 0; g < 4; g++) {
            int row = b_row_base + g * 16;
            int kc  = ks * 2 + b_kc_lane;
            uint32_t addr = sb + SMEM_B_OFF + row * 256 + ((kc ^ (row & 7)) << 4);
            ldmatrix_x4(b[2 * g][0], b[2 * g][1], b[2 * g + 1][0], b[2 * g + 1][1], addr);
        }
        #pragma unroll
        for (int mi = 0; mi < 4; mi++)
            #pragma unroll
            for (int ni = 0; ni < 8; ni++)
                mma_bf16(acc[mi][ni][0], acc[mi][ni][1], acc[mi][ni][2], acc[mi][ni][3],
                         a[mi][0], a[mi][1], a[mi][2], a[mi][3],
                         b[ni][0], b[ni][1]);
    }

    // ---- epilogue: out = xs[m] + ps[n] - 2*acc ----
    const int c_base = n0 + warp_n * 64 + (lane & 3) * 2;
    float2 ps[8];
    #pragma unroll
    for (int ni = 0; ni < 8; ni++)
        ps[ni] = *reinterpret_cast<const float2*>(g_ps + c_base + ni * 8);

    #pragma unroll
    for (int mi = 0; mi < 4; mi++) {
        int r0 = m0 + warp_m * 64 + mi * 16 + (lane >> 2);
        float xs0 = g_xs[r0];
        float xs1 = g_xs[r0 + 8];
        float* o0 = out + (size_t)r0 * C_ROWS + c_base;
        float* o1 = out + (size_t)(r0 + 8) * C_ROWS + c_base;
        #pragma unroll
        for (int ni = 0; ni < 8; ni++) {
            float2 v0, v1;
            v0.x = xs0 + ps[ni].x - 2.0f * acc[mi][ni][0];
            v0.y = xs0 + ps[ni].y - 2.0f * acc[mi][ni][1];
            v1.x = xs1 + ps[ni].x - 2.0f * acc[mi][ni][2];
            v1.y = xs1 + ps[ni].y - 2.0f * acc[mi][ni][3];
            *reinterpret_cast<float2*>(o0 + ni * 8) = v0;
            *reinterpret_cast<float2*>(o1 + ni * 8) = v1;
        }
    }
}

// ============================================================================
extern "C" void kernel_launch(void* const* d_in, const int* in_sizes, int n_in,
                              void* d_out, int out_size) {
    (void)in_sizes; (void)n_in; (void)out_size;
    const float* inp = (const float*)d_in[0];   // inputs [4096,128] fp32
    const float* ker = (const float*)d_in[1];   // kernel [16384,128] fp32
    float* out = (float*)d_out;                 // [4096,16384] fp32

    cudaFuncSetAttribute(gemm_kernel, cudaFuncAttributeMaxDynamicSharedMemorySize, SMEM_TOTAL);

    int total_warps = B_ROWS + C_ROWS;
    normalize_kernel<<<(total_warps * 32 + 255) / 256, 256>>>(inp, ker);

    dim3 grid(C_ROWS / NT, B_ROWS / MT);   // 128 x 32
    gemm_kernel<<<grid, 128, SMEM_TOTAL>>>(out);
}